// round 2
// baseline (speedup 1.0000x reference)
#include <cuda_runtime.h>
#include <cuda_bf16.h>
#include <math.h>

// ---------------- problem constants ----------------
#define NN      512
#define LIN     640
#define LEADS   3

#define L1OUT   322   // conv1: k=5 s=2 p=4
#define L2OUT   161   // conv2: k=7 s=2 p=3
#define L3OUT   79    // conv3: k=9 s=2 p=2

#define C1      64
#define C2      128
#define C3      256

#define FLAT    20224  // 256*79
#define NUMK    100
#define DIMK    5
#define ACTW    500    // NUMK*DIMK
#define FCW_LEN 20374  // FLAT + NUMK + 50

#define KSPLIT  4
#define KCHUNK  5056   // 20224/4, divisible by 16

// ---------------- device scratch ----------------
__device__ float g_inv_sigma[3];
__device__ float g_w1t[LEADS * 5 * C1];          // (ic*5+k, oc)
__device__ float g_w2t[C1 * 7 * C2];             // (ic*7+k, oc)
__device__ float g_w3t[C2 * 9 * C3];             // (ic*9+k, oc)
__device__ float g_x1[NN * C1 * L1OUT];
__device__ float g_x2[NN * C2 * L2OUT];
__device__ float g_flat[NN * FLAT];
__device__ float g_act_part[KSPLIT * NN * ACTW];
__device__ float g_act[NN * ACTW];
__device__ float g_feats[NN * NUMK];

__device__ __forceinline__ float leaky(float x) { return x >= 0.f ? x : 0.2f * x; }

// ---------------- spectral norm: sigma = ||W @ normalize(W^T u)|| ----------------
__global__ void sigma_k(const float* __restrict__ w1, const float* __restrict__ u1,
                        const float* __restrict__ w2, const float* __restrict__ u2,
                        const float* __restrict__ w3, const float* __restrict__ u3) {
    const float* W; const float* U; int O, IK;
    if (blockIdx.x == 0)      { W = w1; U = u1; O = C1; IK = LEADS * 5; }
    else if (blockIdx.x == 1) { W = w2; U = u2; O = C2; IK = C1 * 7;   }
    else                      { W = w3; U = u3; O = C3; IK = C2 * 9;   }

    __shared__ float sv[C2 * 9];       // max IK = 1152
    __shared__ float red[256];
    int tid = threadIdx.x;

    float local = 0.f;
    for (int j = tid; j < IK; j += 256) {
        float v = 0.f;
        for (int i = 0; i < O; i++) v += W[i * IK + j] * U[i];
        sv[j] = v;
        local += v * v;
    }
    red[tid] = local; __syncthreads();
    for (int s = 128; s > 0; s >>= 1) { if (tid < s) red[tid] += red[tid + s]; __syncthreads(); }
    float vscale = 1.f / (sqrtf(red[0]) + 1e-12f);
    __syncthreads();
    for (int j = tid; j < IK; j += 256) sv[j] *= vscale;
    __syncthreads();

    float local2 = 0.f;
    for (int i = tid; i < O; i += 256) {
        float t = 0.f;
        for (int j = 0; j < IK; j++) t += W[i * IK + j] * sv[j];
        local2 += t * t;
    }
    red[tid] = local2; __syncthreads();
    for (int s = 128; s > 0; s >>= 1) { if (tid < s) red[tid] += red[tid + s]; __syncthreads(); }
    if (tid == 0) {
        float nt = red[0];
        float sigma = nt / (sqrtf(nt) + 1e-12f);
        g_inv_sigma[blockIdx.x] = 1.f / sigma;
    }
}

// ---------------- weight transpose + scale: dst[(ic*K+k)*O + oc] = w[oc][ic][k]/sigma ----------------
__global__ void wprep_k(const float* __restrict__ w1, const float* __restrict__ w2,
                        const float* __restrict__ w3) {
    int idx = blockIdx.x * 256 + threadIdx.x;
    if (idx < C2 * 9 * C3) {
        int oc = idx % C3, r = idx / C3;
        g_w3t[idx] = w3[oc * (C2 * 9) + r] * g_inv_sigma[2];
    }
    if (idx < C1 * 7 * C2) {
        int oc = idx % C2, r = idx / C2;
        g_w2t[idx] = w2[oc * (C1 * 7) + r] * g_inv_sigma[1];
    }
    if (idx < LEADS * 5 * C1) {
        int oc = idx % C1, r = idx / C1;
        g_w1t[idx] = w1[oc * (LEADS * 5) + r] * g_inv_sigma[0];
    }
}

// ---------------- conv1: ecg(N,L,3) -> x1(N,64,322), k=5 s=2 p=4 ----------------
__global__ void conv1_k(const float* __restrict__ ecg, const float* __restrict__ b1) {
    __shared__ float sx[LEADS][648];   // 640 + 2*4
    int n = blockIdx.x, tid = threadIdx.x;
    for (int i = tid; i < LEADS * 648; i += 256) {
        int lead = i / 648, p = i % 648;
        int src = p - 4;
        sx[lead][p] = (src >= 0 && src < LIN) ? ecg[n * LIN * LEADS + src * LEADS + lead] : 0.f;
    }
    __syncthreads();
    for (int idx = tid; idx < C1 * L1OUT; idx += 256) {
        int oc = idx / L1OUT, t = idx % L1OUT;
        float acc = b1[oc];
        int base = 2 * t;   // input index 2t-4+k, smem offset +4
        #pragma unroll
        for (int lead = 0; lead < LEADS; lead++)
            #pragma unroll
            for (int k = 0; k < 5; k++)
                acc += g_w1t[(lead * 5 + k) * C1 + oc] * sx[lead][base + k];
        g_x1[n * C1 * L1OUT + oc * L1OUT + t] = leaky(acc);
    }
}

// ---------------- conv2: x1(N,64,322) -> x2(N,128,161), k=7 s=2 p=3 ----------------
#define C2ROW 328      // 322 + 2*3
__global__ void conv2_k(const float* __restrict__ b2) {
    extern __shared__ float sx[];      // [64][328] + slack
    int n = blockIdx.x, tid = threadIdx.x;   // blockDim 128
    for (int i = tid; i < C1 * C2ROW; i += 128) {
        int ic = i / C2ROW, p = i % C2ROW;
        int src = p - 3;
        sx[i] = (src >= 0 && src < L1OUT) ? g_x1[n * C1 * L1OUT + ic * L1OUT + src] : 0.f;
    }
    __syncthreads();
    int oc = tid;
    float bias = b2[oc];
    for (int tb = 0; tb < 21; tb++) {
        int t0 = tb * 8;
        float acc[8];
        #pragma unroll
        for (int q = 0; q < 8; q++) acc[q] = bias;
        for (int ic = 0; ic < C1; ic++) {
            const float* row = sx + ic * C2ROW + 2 * t0;
            float in[21];
            #pragma unroll
            for (int q = 0; q < 21; q++) in[q] = row[q];
            #pragma unroll
            for (int k = 0; k < 7; k++) {
                float w = g_w2t[(ic * 7 + k) * C2 + oc];
                #pragma unroll
                for (int tt = 0; tt < 8; tt++) acc[tt] += w * in[2 * tt + k];
            }
        }
        #pragma unroll
        for (int tt = 0; tt < 8; tt++) {
            int t = t0 + tt;
            if (t < L2OUT) g_x2[n * C2 * L2OUT + oc * L2OUT + t] = leaky(acc[tt]);
        }
    }
}

// ---------------- conv3: x2(N,128,161) -> flat(N, 256*79), k=9 s=2 p=2 ----------------
#define C3ROW 168      // 161 + 2*2 + pad
__global__ void conv3_k(const float* __restrict__ b3) {
    extern __shared__ float sx[];      // [128][168] + slack
    int n = blockIdx.x, tid = threadIdx.x;   // blockDim 256
    for (int i = tid; i < C2 * C3ROW; i += 256) {
        int ic = i / C3ROW, p = i % C3ROW;
        int src = p - 2;
        sx[i] = (src >= 0 && src < L2OUT) ? g_x2[n * C2 * L2OUT + ic * L2OUT + src] : 0.f;
    }
    __syncthreads();
    int oc = tid;
    float bias = b3[oc];
    for (int tb = 0; tb < 10; tb++) {
        int t0 = tb * 8;
        float acc[8];
        #pragma unroll
        for (int q = 0; q < 8; q++) acc[q] = bias;
        for (int ic = 0; ic < C2; ic++) {
            const float* row = sx + ic * C3ROW + 2 * t0;
            float in[23];
            #pragma unroll
            for (int q = 0; q < 23; q++) in[q] = row[q];
            #pragma unroll
            for (int k = 0; k < 9; k++) {
                float w = g_w3t[(ic * 9 + k) * C3 + oc];
                #pragma unroll
                for (int tt = 0; tt < 8; tt++) acc[tt] += w * in[2 * tt + k];
            }
        }
        #pragma unroll
        for (int tt = 0; tt < 8; tt++) {
            int t = t0 + tt;
            if (t < L3OUT) g_flat[n * FLAT + oc * L3OUT + t] = leaky(acc[tt]);
        }
    }
}

// ---------------- GEMM: act = flat(512x20224) @ mb_w(20224x500), split-K ----------------
#define BM 64
#define BN 64
#define BK 16
__global__ void gemm_k(const float* __restrict__ Bmat) {
    __shared__ float As[BK][BM];
    __shared__ float Bs[BK][BN];
    int mb = blockIdx.x, nb = blockIdx.y, kz = blockIdx.z;
    int tid = threadIdx.x;             // 256
    int tx = tid % 16, ty = tid / 16;
    int k_begin = kz * KCHUNK, k_end = k_begin + KCHUNK;
    float acc[4][4];
    #pragma unroll
    for (int i = 0; i < 4; i++)
        #pragma unroll
        for (int j = 0; j < 4; j++) acc[i][j] = 0.f;

    for (int k0 = k_begin; k0 < k_end; k0 += BK) {
        for (int i = tid; i < BM * BK; i += 256) {
            int r = i / BK, c = i % BK;
            As[c][r] = g_flat[(mb * BM + r) * FLAT + k0 + c];
        }
        for (int i = tid; i < BK * BN; i += 256) {
            int r = i / BN, c = i % BN;
            int col = nb * BN + c;
            Bs[r][c] = (col < ACTW) ? Bmat[(k0 + r) * ACTW + col] : 0.f;
        }
        __syncthreads();
        #pragma unroll
        for (int kk = 0; kk < BK; kk++) {
            float a[4], b[4];
            #pragma unroll
            for (int q = 0; q < 4; q++) a[q] = As[kk][ty * 4 + q];
            #pragma unroll
            for (int q = 0; q < 4; q++) b[q] = Bs[kk][tx * 4 + q];
            #pragma unroll
            for (int i = 0; i < 4; i++)
                #pragma unroll
                for (int j = 0; j < 4; j++) acc[i][j] += a[i] * b[j];
        }
        __syncthreads();
    }
    int m0 = mb * BM + ty * 4, n0 = nb * BN + tx * 4;
    #pragma unroll
    for (int i = 0; i < 4; i++)
        #pragma unroll
        for (int j = 0; j < 4; j++) {
            int cc = n0 + j;
            if (cc < ACTW) g_act_part[kz * (NN * ACTW) + (m0 + i) * ACTW + cc] = acc[i][j];
        }
}

__global__ void kreduce_k() {
    int idx = blockIdx.x * 256 + threadIdx.x;
    if (idx < NN * ACTW) {
        float s = 0.f;
        #pragma unroll
        for (int z = 0; z < KSPLIT; z++) s += g_act_part[z * (NN * ACTW) + idx];
        g_act[idx] = s;
    }
}

// ---------------- minibatch discrimination: feats(n,m) = sum_j exp(-L1(act_n_m, act_j_m)) ----------------
__global__ void mbfeat_k() {
    __shared__ float sa[NN * DIMK];    // 512*5 floats
    int m = blockIdx.x, tid = threadIdx.x;   // blockDim 512
    #pragma unroll
    for (int d = 0; d < DIMK; d++)
        sa[tid * DIMK + d] = g_act[tid * ACTW + m * DIMK + d];
    __syncthreads();
    float a0 = sa[tid * DIMK + 0], a1 = sa[tid * DIMK + 1], a2 = sa[tid * DIMK + 2],
          a3 = sa[tid * DIMK + 3], a4 = sa[tid * DIMK + 4];
    float s = 0.f;
    for (int j = 0; j < NN; j++) {
        const float* b = sa + j * DIMK;
        float l = fabsf(a0 - b[0]) + fabsf(a1 - b[1]) + fabsf(a2 - b[2]) +
                  fabsf(a3 - b[3]) + fabsf(a4 - b[4]);
        s += __expf(-l);
    }
    g_feats[tid * NUMK + m] = s;
}

// ---------------- final: out[n] = flat.fc + feats.fc + cond.fc + b ----------------
__global__ void final_k(const int* __restrict__ condition, const float* __restrict__ emb,
                        const float* __restrict__ cond_w, const float* __restrict__ cond_b,
                        const float* __restrict__ fc_w, const float* __restrict__ fc_b,
                        float* __restrict__ out) {
    int n = blockIdx.x, tid = threadIdx.x;   // blockDim 256
    float s = 0.f;
    const float* fr = g_flat + n * FLAT;
    for (int i = tid; i < FLAT; i += 256) s += fr[i] * fc_w[i];
    for (int i = tid; i < NUMK; i += 256) s += g_feats[n * NUMK + i] * fc_w[FLAT + i];
    float e = emb[condition[n]];
    for (int i = tid; i < 50; i += 256) s += (e * cond_w[i] + cond_b[i]) * fc_w[FLAT + NUMK + i];
    __shared__ float red[256];
    red[tid] = s; __syncthreads();
    for (int st = 128; st > 0; st >>= 1) { if (tid < st) red[tid] += red[tid + st]; __syncthreads(); }
    if (tid == 0) out[n] = red[0] + fc_b[0];
}

// ---------------- launch ----------------
extern "C" void kernel_launch(void* const* d_in, const int* in_sizes, int n_in,
                              void* d_out, int out_size) {
    const float* ecg       = (const float*)d_in[0];
    const int*   condition = (const int*)  d_in[1];
    const float* w1        = (const float*)d_in[2];
    const float* b1        = (const float*)d_in[3];
    const float* u1        = (const float*)d_in[4];
    const float* w2        = (const float*)d_in[5];
    const float* b2        = (const float*)d_in[6];
    const float* u2        = (const float*)d_in[7];
    const float* w3        = (const float*)d_in[8];
    const float* b3        = (const float*)d_in[9];
    const float* u3        = (const float*)d_in[10];
    const float* emb       = (const float*)d_in[11];
    const float* cond_w    = (const float*)d_in[12];
    const float* cond_b    = (const float*)d_in[13];
    const float* mb_w      = (const float*)d_in[14];
    const float* fc_w      = (const float*)d_in[15];
    const float* fc_b      = (const float*)d_in[16];
    float* out = (float*)d_out;

    size_t smem2 = (C1 * C2ROW + 64) * sizeof(float);   // ~84 KB
    size_t smem3 = (C2 * C3ROW + 64) * sizeof(float);   // ~86 KB
    cudaFuncSetAttribute(conv2_k, cudaFuncAttributeMaxDynamicSharedMemorySize, (int)smem2);
    cudaFuncSetAttribute(conv3_k, cudaFuncAttributeMaxDynamicSharedMemorySize, (int)smem3);

    sigma_k<<<3, 256>>>(w1, u1, w2, u2, w3, u3);
    wprep_k<<<(C2 * 9 * C3 + 255) / 256, 256>>>(w1, w2, w3);
    conv1_k<<<NN, 256>>>(ecg, b1);
    conv2_k<<<NN, 128, smem2>>>(b2);
    conv3_k<<<NN, 256, smem3>>>(b3);
    gemm_k<<<dim3(NN / BM, (ACTW + BN - 1) / BN, KSPLIT), 256>>>(mb_w);
    kreduce_k<<<(NN * ACTW + 255) / 256, 256>>>();
    mbfeat_k<<<NUMK, NN>>>();
    final_k<<<NN, 256>>>(condition, emb, cond_w, cond_b, fc_w, fc_b, out);
}

// round 5
// speedup vs baseline: 1.8435x; 1.8435x over previous
#include <cuda_runtime.h>
#include <math.h>

// ---------------- problem constants ----------------
#define NN      512
#define LIN     640
#define LEADS   3
#define T1      322
#define T2      161
#define T3      79
#define C1      64
#define C2      128
#define C3      256
#define ER      648     // ecgT padded rows (pad 4 each side)
#define X1R     336     // x1 padded rows (valid p=3..324)
#define X2R     168     // x2 padded rows (valid p=2..162)
#define FLAT    20224
#define NUMK    100
#define DIMK    5
#define ACTW    500
#define GJT     32
#define GKS     16
#define GKC     1264    // 20224/16
#define FCH     64
#define FPERC   316     // 64*316 = 20224

// ---------------- device scratch (n-major layouts) ----------------
__device__ float g_inv_sigma[3];
__device__ float g_w1t[15 * C1];        // (ik, oc)
__device__ float g_w2t[448 * C2];
__device__ float g_w3t[1152 * C3];
__device__ float g_ecgT[LEADS * ER * NN];       // [lead][p][n]
__device__ float g_x1[C1 * X1R * NN];           // [ic][p][n]
__device__ float g_x2[C2 * X2R * NN];
__device__ float g_flat[FLAT * NN];             // [f][n], f = oc*79+t
__device__ float g_act_part[GKS * ACTW * NN];
__device__ float g_act[ACTW * NN];              // [j][n]
__device__ float g_feats[NUMK * NN];            // [m][n]
__device__ float g_fpart[FCH * NN];

typedef unsigned long long ull;

__device__ __forceinline__ void ffma2(ull& d, const ull a, const ull b) {
    asm("fma.rn.f32x2 %0, %1, %2, %0;" : "+l"(d) : "l"(a), "l"(b));
}
__device__ __forceinline__ ull pack2(float x, float y) {
    ull u; asm("mov.b64 %0, {%1,%2};" : "=l"(u) : "f"(x), "f"(y)); return u;
}
__device__ __forceinline__ float2 unpack(ull u) {
    float2 f; asm("mov.b64 {%0,%1}, %2;" : "=f"(f.x), "=f"(f.y) : "l"(u)); return f;
}
__device__ __forceinline__ float leaky(float x) { return x >= 0.f ? x : 0.2f * x; }

// ---------------- spectral norm: sigma = ||W @ normalize(W^T u)|| ----------------
__global__ void sigma_k(const float* __restrict__ w1, const float* __restrict__ u1,
                        const float* __restrict__ w2, const float* __restrict__ u2,
                        const float* __restrict__ w3, const float* __restrict__ u3) {
    const float* W; const float* U; int O, IK;
    if (blockIdx.x == 0)      { W = w1; U = u1; O = C1; IK = 15;   }
    else if (blockIdx.x == 1) { W = w2; U = u2; O = C2; IK = 448;  }
    else                      { W = w3; U = u3; O = C3; IK = 1152; }

    __shared__ float sv[1152];
    __shared__ float red[256];
    int tid = threadIdx.x;

    float local = 0.f;
    for (int j = tid; j < IK; j += 256) {
        float v = 0.f;
        for (int i = 0; i < O; i++) v += W[i * IK + j] * U[i];
        sv[j] = v;
        local += v * v;
    }
    red[tid] = local; __syncthreads();
    for (int s = 128; s > 0; s >>= 1) { if (tid < s) red[tid] += red[tid + s]; __syncthreads(); }
    float vscale = 1.f / (sqrtf(red[0]) + 1e-12f);
    __syncthreads();
    for (int j = tid; j < IK; j += 256) sv[j] *= vscale;
    __syncthreads();

    float local2 = 0.f;
    for (int i = tid; i < O; i += 256) {
        float t = 0.f;
        for (int j = 0; j < IK; j++) t += W[i * IK + j] * sv[j];
        local2 += t * t;
    }
    red[tid] = local2; __syncthreads();
    for (int s = 128; s > 0; s >>= 1) { if (tid < s) red[tid] += red[tid + s]; __syncthreads(); }
    if (tid == 0) {
        float nt = red[0];
        float sigma = nt / (sqrtf(nt) + 1e-12f);
        g_inv_sigma[blockIdx.x] = 1.f / sigma;
    }
}

// ---------------- weight transpose + scale ----------------
__global__ void wprep_k(const float* __restrict__ w1, const float* __restrict__ w2,
                        const float* __restrict__ w3) {
    int idx = blockIdx.x * 256 + threadIdx.x;
    if (idx < 1152 * C3) {
        int oc = idx % C3, r = idx / C3;
        g_w3t[idx] = w3[oc * 1152 + r] * g_inv_sigma[2];
    }
    if (idx < 448 * C2) {
        int oc = idx % C2, r = idx / C2;
        g_w2t[idx] = w2[oc * 448 + r] * g_inv_sigma[1];
    }
    if (idx < 15 * C1) {
        int oc = idx % C1, r = idx / C1;
        g_w1t[idx] = w1[oc * 15 + r] * g_inv_sigma[0];
    }
}

// ---------------- transpose ecg(N,L,3) -> ecgT[lead][p][n], zero-padded ----------------
__global__ void ecgT_k(const float* __restrict__ ecg) {
    int idx = blockIdx.x * 256 + threadIdx.x;
    if (idx >= LEADS * ER * NN) return;
    int n = idx & (NN - 1);
    int rem = idx >> 9;
    int p = rem % ER;
    int lead = rem / ER;
    int t = p - 4;
    g_ecgT[idx] = (t >= 0 && t < LIN) ? ecg[(size_t)n * (LIN * LEADS) + t * LEADS + lead] : 0.f;
}

// ---------------- conv1: ecgT -> x1[ic][p][n], k=5 s=2 p=4 ----------------
__global__ void conv1_k(const float* __restrict__ b1) {
    __shared__ ull sw[15 * 16];
    int tid = threadIdx.x;                 // 256
    int t0 = blockIdx.x * 2;               // both t valid (322 even)
    int oc0 = blockIdx.y * 16;
    for (int i = tid; i < 15 * 16; i += 256) {
        int j = i & 15, r = i >> 4;
        float w = g_w1t[r * C1 + oc0 + j];
        sw[i] = pack2(w, w);
    }
    ull acc[16][2];
    #pragma unroll
    for (int j = 0; j < 16; j++) { float b = b1[oc0 + j]; acc[j][0] = acc[j][1] = pack2(b, b); }
    __syncthreads();
    #pragma unroll
    for (int lead = 0; lead < LEADS; lead++) {
        const ull* xp = reinterpret_cast<const ull*>(g_ecgT + ((size_t)lead * ER + 2 * t0) * NN) + tid;
        ull in[7];
        #pragma unroll
        for (int r = 0; r < 7; r++) in[r] = __ldg(xp + r * (NN / 2));
        #pragma unroll
        for (int k = 0; k < 5; k++) {
            #pragma unroll
            for (int j = 0; j < 16; j++) {
                ull w = sw[(lead * 5 + k) * 16 + j];
                ffma2(acc[j][0], in[k], w);
                ffma2(acc[j][1], in[k + 2], w);
            }
        }
    }
    #pragma unroll
    for (int j = 0; j < 16; j++) {
        int oc = oc0 + j;
        float2 v0 = unpack(acc[j][0]);
        float2 v1 = unpack(acc[j][1]);
        v0.x = leaky(v0.x); v0.y = leaky(v0.y);
        v1.x = leaky(v1.x); v1.y = leaky(v1.y);
        float2* o = reinterpret_cast<float2*>(g_x1 + ((size_t)oc * X1R + (t0 + 3)) * NN);
        o[tid] = v0;
        o[NN / 2 + tid] = v1;
    }
}

// ---------------- conv2: x1 -> x2[ic][p][n], k=7 s=2 p=3 ----------------
__global__ void conv2_k(const float* __restrict__ b2) {
    __shared__ ull sw[32 * 7 * 16];        // 28.7 KB
    int tid = threadIdx.x;                 // 256
    int t0 = blockIdx.x * 2;
    int oc0 = blockIdx.y * 16;
    bool has_t1 = (t0 + 1) < T2;
    ull acc[16][2];
    #pragma unroll
    for (int j = 0; j < 16; j++) { float b = b2[oc0 + j]; acc[j][0] = acc[j][1] = pack2(b, b); }
    for (int ch = 0; ch < 2; ch++) {
        int ic0 = ch * 32;
        __syncthreads();
        for (int i = tid; i < 32 * 7 * 16; i += 256) {
            int j = i & 15, row = i >> 4;  // row = icl*7+k
            float w = g_w2t[(ic0 * 7 + row) * C2 + oc0 + j];
            sw[i] = pack2(w, w);
        }
        __syncthreads();
        for (int icl = 0; icl < 32; icl++) {
            const ull* xp = reinterpret_cast<const ull*>(g_x1 + ((size_t)(ic0 + icl) * X1R + 2 * t0) * NN) + tid;
            ull in[9];
            #pragma unroll
            for (int r = 0; r < 9; r++) in[r] = __ldg(xp + r * (NN / 2));
            #pragma unroll
            for (int k = 0; k < 7; k++) {
                #pragma unroll
                for (int j = 0; j < 16; j++) {
                    ull w = sw[(icl * 7 + k) * 16 + j];
                    ffma2(acc[j][0], in[k], w);
                    ffma2(acc[j][1], in[k + 2], w);
                }
            }
        }
    }
    #pragma unroll
    for (int j = 0; j < 16; j++) {
        int oc = oc0 + j;
        float2 v0 = unpack(acc[j][0]);
        float2 v1 = unpack(acc[j][1]);
        v0.x = leaky(v0.x); v0.y = leaky(v0.y);
        v1.x = leaky(v1.x); v1.y = leaky(v1.y);
        float2* o = reinterpret_cast<float2*>(g_x2 + ((size_t)oc * X2R + (t0 + 2)) * NN);
        o[tid] = v0;
        if (has_t1) o[NN / 2 + tid] = v1;
    }
}

// ---------------- conv3: x2 -> flat[oc*79+t][n], k=9 s=2 p=2 ----------------
__global__ void conv3_k(const float* __restrict__ b3) {
    __shared__ ull sw[32 * 9 * 16];        // 36.9 KB
    int tid = threadIdx.x;                 // 256
    int t0 = blockIdx.x * 2;
    int oc0 = blockIdx.y * 16;
    bool has_t1 = (t0 + 1) < T3;
    ull acc[16][2];
    #pragma unroll
    for (int j = 0; j < 16; j++) { float b = b3[oc0 + j]; acc[j][0] = acc[j][1] = pack2(b, b); }
    for (int ch = 0; ch < 4; ch++) {
        int ic0 = ch * 32;
        __syncthreads();
        for (int i = tid; i < 32 * 9 * 16; i += 256) {
            int j = i & 15, row = i >> 4;  // row = icl*9+k
            float w = g_w3t[(ic0 * 9 + row) * C3 + oc0 + j];
            sw[i] = pack2(w, w);
        }
        __syncthreads();
        for (int icl = 0; icl < 32; icl++) {
            const ull* xp = reinterpret_cast<const ull*>(g_x2 + ((size_t)(ic0 + icl) * X2R + 2 * t0) * NN) + tid;
            ull in[11];
            #pragma unroll
            for (int r = 0; r < 11; r++) in[r] = __ldg(xp + r * (NN / 2));
            #pragma unroll
            for (int k = 0; k < 9; k++) {
                #pragma unroll
                for (int j = 0; j < 16; j++) {
                    ull w = sw[(icl * 9 + k) * 16 + j];
                    ffma2(acc[j][0], in[k], w);
                    ffma2(acc[j][1], in[k + 2], w);
                }
            }
        }
    }
    #pragma unroll
    for (int j = 0; j < 16; j++) {
        int oc = oc0 + j;
        float2 v0 = unpack(acc[j][0]);
        float2 v1 = unpack(acc[j][1]);
        v0.x = leaky(v0.x); v0.y = leaky(v0.y);
        v1.x = leaky(v1.x); v1.y = leaky(v1.y);
        float2* o = reinterpret_cast<float2*>(g_flat + ((size_t)oc * T3 + t0) * NN);
        o[tid] = v0;
        if (has_t1) o[NN / 2 + tid] = v1;
    }
}

// ---------------- GEMM: act[j][n] = sum_f mb_w[f][j] * flat[f][n], split-K ----------------
__global__ void gemm_k(const float* __restrict__ mbw) {
    __shared__ ull sw[64 * GJT];           // 16 KB
    int tid = threadIdx.x;                 // 128; each thread covers 4 n
    int j0 = blockIdx.x * GJT;
    int kz = blockIdx.y;
    int f_begin = kz * GKC, f_end = f_begin + GKC;
    ull acc[GJT][2];
    #pragma unroll
    for (int j = 0; j < GJT; j++) acc[j][0] = acc[j][1] = 0ULL;

    for (int f0 = f_begin; f0 < f_end; f0 += 64) {
        int cnt = min(64, f_end - f0);
        __syncthreads();
        for (int i = tid; i < cnt * GJT; i += 128) {
            int j = i & (GJT - 1), r = i / GJT;
            int col = j0 + j;
            float w = (col < ACTW) ? mbw[(size_t)(f0 + r) * ACTW + col] : 0.f;
            sw[r * GJT + j] = pack2(w, w);
        }
        __syncthreads();
        for (int r = 0; r < cnt; r++) {
            const ull* fp = reinterpret_cast<const ull*>(g_flat + (size_t)(f0 + r) * NN) + 2 * tid;
            ull a0 = __ldg(fp), a1 = __ldg(fp + 1);
            #pragma unroll
            for (int j = 0; j < GJT; j++) {
                ull w = sw[r * GJT + j];
                ffma2(acc[j][0], a0, w);
                ffma2(acc[j][1], a1, w);
            }
        }
    }
    for (int j = 0; j < GJT; j++) {
        int col = j0 + j;
        if (col < ACTW) {
            float2* bp = reinterpret_cast<float2*>(g_act_part + ((size_t)kz * ACTW + col) * NN);
            bp[2 * tid]     = unpack(acc[j][0]);
            bp[2 * tid + 1] = unpack(acc[j][1]);
        }
    }
}

__global__ void kreduce_k() {
    int idx = blockIdx.x * 256 + threadIdx.x;
    if (idx < ACTW * NN) {
        float s = 0.f;
        #pragma unroll
        for (int z = 0; z < GKS; z++) s += g_act_part[(size_t)z * (ACTW * NN) + idx];
        g_act[idx] = s;
    }
}

// ---------------- minibatch discrimination ----------------
__global__ void mbfeat_k() {
    __shared__ float sa[NN * DIMK];
    int m = blockIdx.x, tid = threadIdx.x;     // 512 threads
    #pragma unroll
    for (int d = 0; d < DIMK; d++)
        sa[tid * DIMK + d] = g_act[(size_t)(m * DIMK + d) * NN + tid];
    __syncthreads();
    float a0 = sa[tid * DIMK + 0], a1 = sa[tid * DIMK + 1], a2 = sa[tid * DIMK + 2],
          a3 = sa[tid * DIMK + 3], a4 = sa[tid * DIMK + 4];
    float s = 0.f;
    for (int j = 0; j < NN; j++) {
        const float* b = sa + j * DIMK;
        float l = fabsf(a0 - b[0]) + fabsf(a1 - b[1]) + fabsf(a2 - b[2]) +
                  fabsf(a3 - b[3]) + fabsf(a4 - b[4]);
        s += __expf(-l);
    }
    g_feats[(size_t)m * NN + tid] = s;
}

// ---------------- final dot: partial over f-chunks, then reduce ----------------
__global__ void final_part_k(const float* __restrict__ fc_w) {
    int tid = threadIdx.x;                     // 512
    int base = blockIdx.x * FPERC;
    float s = 0.f;
    for (int r = 0; r < FPERC; r++) {
        int f = base + r;
        s += g_flat[(size_t)f * NN + tid] * __ldg(fc_w + f);
    }
    g_fpart[(size_t)blockIdx.x * NN + tid] = s;
}

__global__ void final_red_k(const int* __restrict__ condition, const float* __restrict__ emb,
                            const float* __restrict__ cond_w, const float* __restrict__ cond_b,
                            const float* __restrict__ fc_w, const float* __restrict__ fc_b,
                            float* __restrict__ out) {
    int n = threadIdx.x;                       // 512
    float s = fc_b[0];
    for (int b = 0; b < FCH; b++) s += g_fpart[(size_t)b * NN + n];
    for (int m = 0; m < NUMK; m++) s += g_feats[(size_t)m * NN + n] * fc_w[FLAT + m];
    float e = emb[condition[n]];
    for (int i = 0; i < 50; i++) s += (e * cond_w[i] + cond_b[i]) * fc_w[FLAT + NUMK + i];
    out[n] = s;
}

// ---------------- launch ----------------
extern "C" void kernel_launch(void* const* d_in, const int* in_sizes, int n_in,
                              void* d_out, int out_size) {
    const float* ecg       = (const float*)d_in[0];
    const int*   condition = (const int*)  d_in[1];
    const float* w1        = (const float*)d_in[2];
    const float* b1        = (const float*)d_in[3];
    const float* u1        = (const float*)d_in[4];
    const float* w2        = (const float*)d_in[5];
    const float* b2        = (const float*)d_in[6];
    const float* u2        = (const float*)d_in[7];
    const float* w3        = (const float*)d_in[8];
    const float* b3        = (const float*)d_in[9];
    const float* u3        = (const float*)d_in[10];
    const float* emb       = (const float*)d_in[11];
    const float* cond_w    = (const float*)d_in[12];
    const float* cond_b    = (const float*)d_in[13];
    const float* mb_w      = (const float*)d_in[14];
    const float* fc_w      = (const float*)d_in[15];
    const float* fc_b      = (const float*)d_in[16];
    float* out = (float*)d_out;

    sigma_k<<<3, 256>>>(w1, u1, w2, u2, w3, u3);
    wprep_k<<<(1152 * C3 + 255) / 256, 256>>>(w1, w2, w3);
    ecgT_k<<<(LEADS * ER * NN + 255) / 256, 256>>>(ecg);
    conv1_k<<<dim3(T1 / 2, C1 / 16), 256>>>(b1);
    conv2_k<<<dim3((T2 + 1) / 2, C2 / 16), 256>>>(b2);
    conv3_k<<<dim3((T3 + 1) / 2, C3 / 16), 256>>>(b3);
    gemm_k<<<dim3((ACTW + GJT - 1) / GJT, GKS), 128>>>(mb_w);
    kreduce_k<<<(ACTW * NN + 255) / 256, 256>>>();
    mbfeat_k<<<NUMK, NN>>>();
    final_part_k<<<FCH, NN>>>(fc_w);
    final_red_k<<<1, NN>>>(condition, emb, cond_w, cond_b, fc_w, fc_b, out);
}

// round 7
// speedup vs baseline: 1.9586x; 1.0625x over previous
#include <cuda_runtime.h>
#include <math.h>

// ---------------- problem constants ----------------
#define NN      512
#define LIN     640
#define LEADS   3
#define T1      322
#define T2      161
#define T3      79
#define C1      64
#define C2      128
#define C3      256
#define ER      648     // ecgT padded rows (pad 4 each side)
#define X1R     336     // x1 padded rows (valid p=3..324)
#define X2R     168     // x2 padded rows (valid p=2..162)
#define FLAT    20224
#define NUMK    100
#define DIMK    5
#define ACTW    500
#define GJT     32
#define GKS     32
#define GKC     632     // 20224/32
#define GWB     158     // weight-stage rows; 632 = 4*158
#define FCH     64
#define FPERC   316     // 64*316 = 20224

// ---------------- device scratch (n-major layouts) ----------------
__device__ float g_inv_sigma[3];
__device__ float g_w1t[15 * C1];        // (ik, oc)
__device__ float g_w2t[448 * C2];
__device__ float g_w3t[1152 * C3];
__device__ float g_ecgT[LEADS * ER * NN];       // [lead][p][n]
__device__ float g_x1[C1 * X1R * NN];           // [ic][p][n]
__device__ float g_x2[C2 * X2R * NN];
__device__ float g_flat[FLAT * NN];             // [f][n], f = oc*79+t
__device__ float g_act_part[GKS * ACTW * NN];
__device__ float g_act[ACTW * NN];              // [j][n]
__device__ float g_feats[NUMK * NN];            // [m][n]
__device__ float g_fpart[FCH * NN];

typedef unsigned long long ull;

__device__ __forceinline__ void ffma2(ull& d, const ull a, const ull b) {
    asm("fma.rn.f32x2 %0, %1, %2, %0;" : "+l"(d) : "l"(a), "l"(b));
}
__device__ __forceinline__ ull add2(const ull a, const ull b) {
    ull d; asm("add.rn.f32x2 %0, %1, %2;" : "=l"(d) : "l"(a), "l"(b)); return d;
}
__device__ __forceinline__ ull abs2(const ull a) {
    return a & 0x7FFFFFFF7FFFFFFFULL;
}
__device__ __forceinline__ ull pack2(float x, float y) {
    ull u; asm("mov.b64 %0, {%1,%2};" : "=l"(u) : "f"(x), "f"(y)); return u;
}
__device__ __forceinline__ float2 unpack(ull u) {
    float2 f; asm("mov.b64 {%0,%1}, %2;" : "=f"(f.x), "=f"(f.y) : "l"(u)); return f;
}
__device__ __forceinline__ float leaky(float x) { return x >= 0.f ? x : 0.2f * x; }

// ---------------- spectral norm ----------------
__global__ void sigma_k(const float* __restrict__ w1, const float* __restrict__ u1,
                        const float* __restrict__ w2, const float* __restrict__ u2,
                        const float* __restrict__ w3, const float* __restrict__ u3) {
    const float* W; const float* U; int O, IK;
    if (blockIdx.x == 0)      { W = w1; U = u1; O = C1; IK = 15;   }
    else if (blockIdx.x == 1) { W = w2; U = u2; O = C2; IK = 448;  }
    else                      { W = w3; U = u3; O = C3; IK = 1152; }

    __shared__ float sv[1152];
    __shared__ float red[256];
    int tid = threadIdx.x;

    float local = 0.f;
    for (int j = tid; j < IK; j += 256) {
        float v = 0.f;
        for (int i = 0; i < O; i++) v += W[i * IK + j] * U[i];
        sv[j] = v;
        local += v * v;
    }
    red[tid] = local; __syncthreads();
    for (int s = 128; s > 0; s >>= 1) { if (tid < s) red[tid] += red[tid + s]; __syncthreads(); }
    float vscale = 1.f / (sqrtf(red[0]) + 1e-12f);
    __syncthreads();
    for (int j = tid; j < IK; j += 256) sv[j] *= vscale;
    __syncthreads();

    float local2 = 0.f;
    for (int i = tid; i < O; i += 256) {
        float t = 0.f;
        for (int j = 0; j < IK; j++) t += W[i * IK + j] * sv[j];
        local2 += t * t;
    }
    red[tid] = local2; __syncthreads();
    for (int s = 128; s > 0; s >>= 1) { if (tid < s) red[tid] += red[tid + s]; __syncthreads(); }
    if (tid == 0) {
        float nt = red[0];
        float sigma = nt / (sqrtf(nt) + 1e-12f);
        g_inv_sigma[blockIdx.x] = 1.f / sigma;
    }
}

// ---------------- weight transpose + scale ----------------
__global__ void wprep_k(const float* __restrict__ w1, const float* __restrict__ w2,
                        const float* __restrict__ w3) {
    int idx = blockIdx.x * 256 + threadIdx.x;
    if (idx < 1152 * C3) {
        int oc = idx % C3, r = idx / C3;
        g_w3t[idx] = w3[oc * 1152 + r] * g_inv_sigma[2];
    }
    if (idx < 448 * C2) {
        int oc = idx % C2, r = idx / C2;
        g_w2t[idx] = w2[oc * 448 + r] * g_inv_sigma[1];
    }
    if (idx < 15 * C1) {
        int oc = idx % C1, r = idx / C1;
        g_w1t[idx] = w1[oc * 15 + r] * g_inv_sigma[0];
    }
}

// ---------------- transpose ecg(N,L,3) -> ecgT[lead][p][n] ----------------
__global__ void ecgT_k(const float* __restrict__ ecg) {
    int idx = blockIdx.x * 256 + threadIdx.x;
    if (idx >= LEADS * ER * NN) return;
    int n = idx & (NN - 1);
    int rem = idx >> 9;
    int p = rem % ER;
    int lead = rem / ER;
    int t = p - 4;
    g_ecgT[idx] = (t >= 0 && t < LIN) ? ecg[(size_t)n * (LIN * LEADS) + t * LEADS + lead] : 0.f;
}

// ---------------- conv1: ecgT -> x1, k=5 s=2 p=4 ----------------
__global__ void conv1_k(const float* __restrict__ b1) {
    __shared__ ull sw[15 * 16];
    int tid = threadIdx.x;                 // 256
    int t0 = blockIdx.x * 2;
    int oc0 = blockIdx.y * 16;
    for (int i = tid; i < 15 * 16; i += 256) {
        int j = i & 15, r = i >> 4;
        float w = g_w1t[r * C1 + oc0 + j];
        sw[i] = pack2(w, w);
    }
    ull acc[16][2];
    #pragma unroll
    for (int j = 0; j < 16; j++) { float b = b1[oc0 + j]; acc[j][0] = acc[j][1] = pack2(b, b); }
    __syncthreads();
    #pragma unroll
    for (int lead = 0; lead < LEADS; lead++) {
        const ull* xp = reinterpret_cast<const ull*>(g_ecgT + ((size_t)lead * ER + 2 * t0) * NN) + tid;
        ull in[7];
        #pragma unroll
        for (int r = 0; r < 7; r++) in[r] = __ldg(xp + r * (NN / 2));
        #pragma unroll
        for (int k = 0; k < 5; k++) {
            #pragma unroll
            for (int j = 0; j < 16; j++) {
                ull w = sw[(lead * 5 + k) * 16 + j];
                ffma2(acc[j][0], in[k], w);
                ffma2(acc[j][1], in[k + 2], w);
            }
        }
    }
    #pragma unroll
    for (int j = 0; j < 16; j++) {
        int oc = oc0 + j;
        float2 v0 = unpack(acc[j][0]);
        float2 v1 = unpack(acc[j][1]);
        v0.x = leaky(v0.x); v0.y = leaky(v0.y);
        v1.x = leaky(v1.x); v1.y = leaky(v1.y);
        float2* o = reinterpret_cast<float2*>(g_x1 + ((size_t)oc * X1R + (t0 + 3)) * NN);
        o[tid] = v0;
        o[NN / 2 + tid] = v1;
    }
}

// ---------------- conv2: x1 -> x2, k=7 s=2 p=3, pipelined ----------------
__global__ __launch_bounds__(256, 2) void conv2_k(const float* __restrict__ b2) {
    __shared__ ull sw[32 * 7 * 16];        // 28.7 KB
    int tid = threadIdx.x;                 // 256
    int t0 = blockIdx.x * 2;
    int oc0 = blockIdx.y * 16;
    bool has_t1 = (t0 + 1) < T2;
    ull acc[16][2];
    #pragma unroll
    for (int j = 0; j < 16; j++) { float b = b2[oc0 + j]; acc[j][0] = acc[j][1] = pack2(b, b); }

    const ull* xb = reinterpret_cast<const ull*>(g_x1) + (size_t)2 * t0 * (NN / 2) + tid;
    ull bufA[9], bufB[9];
    #pragma unroll
    for (int r = 0; r < 9; r++) bufA[r] = __ldg(xb + r * (NN / 2));   // ic = 0

    for (int ch = 0; ch < 2; ch++) {
        int ic0 = ch * 32;
        __syncthreads();
        for (int i = tid; i < 32 * 7 * 16; i += 256) {
            int j = i & 15, row = i >> 4;
            float w = g_w2t[(ic0 * 7 + row) * C2 + oc0 + j];
            sw[i] = pack2(w, w);
        }
        __syncthreads();
        #pragma unroll 1
        for (int icl = 0; icl < 32; icl += 2) {
            const ull* xpB = xb + (size_t)(ic0 + icl + 1) * X1R * (NN / 2);
            #pragma unroll
            for (int r = 0; r < 9; r++) bufB[r] = __ldg(xpB + r * (NN / 2));
            #pragma unroll
            for (int k = 0; k < 7; k++)
                #pragma unroll
                for (int j = 0; j < 16; j++) {
                    ull w = sw[(icl * 7 + k) * 16 + j];
                    ffma2(acc[j][0], bufA[k], w);
                    ffma2(acc[j][1], bufA[k + 2], w);
                }
            int nic = ic0 + icl + 2;
            if (nic < C1) {
                const ull* xpA = xb + (size_t)nic * X1R * (NN / 2);
                #pragma unroll
                for (int r = 0; r < 9; r++) bufA[r] = __ldg(xpA + r * (NN / 2));
            }
            #pragma unroll
            for (int k = 0; k < 7; k++)
                #pragma unroll
                for (int j = 0; j < 16; j++) {
                    ull w = sw[((icl + 1) * 7 + k) * 16 + j];
                    ffma2(acc[j][0], bufB[k], w);
                    ffma2(acc[j][1], bufB[k + 2], w);
                }
        }
    }
    #pragma unroll
    for (int j = 0; j < 16; j++) {
        int oc = oc0 + j;
        float2 v0 = unpack(acc[j][0]);
        float2 v1 = unpack(acc[j][1]);
        v0.x = leaky(v0.x); v0.y = leaky(v0.y);
        v1.x = leaky(v1.x); v1.y = leaky(v1.y);
        float2* o = reinterpret_cast<float2*>(g_x2 + ((size_t)oc * X2R + (t0 + 2)) * NN);
        o[tid] = v0;
        if (has_t1) o[NN / 2 + tid] = v1;
    }
}

// ---------------- conv3: x2 -> flat, k=9 s=2 p=2, pipelined ----------------
__global__ __launch_bounds__(256, 2) void conv3_k(const float* __restrict__ b3) {
    __shared__ ull sw[32 * 9 * 16];        // 36.9 KB
    int tid = threadIdx.x;                 // 256
    int t0 = blockIdx.x * 2;
    int oc0 = blockIdx.y * 16;
    bool has_t1 = (t0 + 1) < T3;
    ull acc[16][2];
    #pragma unroll
    for (int j = 0; j < 16; j++) { float b = b3[oc0 + j]; acc[j][0] = acc[j][1] = pack2(b, b); }

    const ull* xb = reinterpret_cast<const ull*>(g_x2) + (size_t)2 * t0 * (NN / 2) + tid;
    ull bufA[11], bufB[11];
    #pragma unroll
    for (int r = 0; r < 11; r++) bufA[r] = __ldg(xb + r * (NN / 2));  // ic = 0

    for (int ch = 0; ch < 4; ch++) {
        int ic0 = ch * 32;
        __syncthreads();
        for (int i = tid; i < 32 * 9 * 16; i += 256) {
            int j = i & 15, row = i >> 4;
            float w = g_w3t[(ic0 * 9 + row) * C3 + oc0 + j];
            sw[i] = pack2(w, w);
        }
        __syncthreads();
        #pragma unroll 1
        for (int icl = 0; icl < 32; icl += 2) {
            const ull* xpB = xb + (size_t)(ic0 + icl + 1) * X2R * (NN / 2);
            #pragma unroll
            for (int r = 0; r < 11; r++) bufB[r] = __ldg(xpB + r * (NN / 2));
            #pragma unroll
            for (int k = 0; k < 9; k++)
                #pragma unroll
                for (int j = 0; j < 16; j++) {
                    ull w = sw[(icl * 9 + k) * 16 + j];
                    ffma2(acc[j][0], bufA[k], w);
                    ffma2(acc[j][1], bufA[k + 2], w);
                }
            int nic = ic0 + icl + 2;
            if (nic < C2) {
                const ull* xpA = xb + (size_t)nic * X2R * (NN / 2);
                #pragma unroll
                for (int r = 0; r < 11; r++) bufA[r] = __ldg(xpA + r * (NN / 2));
            }
            #pragma unroll
            for (int k = 0; k < 9; k++)
                #pragma unroll
                for (int j = 0; j < 16; j++) {
                    ull w = sw[((icl + 1) * 9 + k) * 16 + j];
                    ffma2(acc[j][0], bufB[k], w);
                    ffma2(acc[j][1], bufB[k + 2], w);
                }
        }
    }
    #pragma unroll
    for (int j = 0; j < 16; j++) {
        int oc = oc0 + j;
        float2 v0 = unpack(acc[j][0]);
        float2 v1 = unpack(acc[j][1]);
        v0.x = leaky(v0.x); v0.y = leaky(v0.y);
        v1.x = leaky(v1.x); v1.y = leaky(v1.y);
        float2* o = reinterpret_cast<float2*>(g_flat + ((size_t)oc * T3 + t0) * NN);
        o[tid] = v0;
        if (has_t1) o[NN / 2 + tid] = v1;
    }
}

// ---------------- GEMM: act[j][n] = sum_f mb_w[f][j] * flat[f][n], split-K, pipelined ----------------
__global__ __launch_bounds__(128, 3) void gemm_k(const float* __restrict__ mbw) {
    __shared__ ull sw[GWB * GJT];          // 40.4 KB
    int tid = threadIdx.x;                 // 128; each thread covers 4 n
    int j0 = blockIdx.x * GJT;
    int kz = blockIdx.y;
    int f_begin = kz * GKC, f_end = f_begin + GKC;
    ull acc[GJT][2];
    #pragma unroll
    for (int j = 0; j < GJT; j++) acc[j][0] = acc[j][1] = 0ULL;

    const ull* fbase = reinterpret_cast<const ull*>(g_flat);
    ull a0A = __ldg(fbase + (size_t)f_begin * (NN / 2) + 2 * tid);
    ull a1A = __ldg(fbase + (size_t)f_begin * (NN / 2) + 2 * tid + 1);
    ull a0B, a1B;

    for (int f0 = f_begin; f0 < f_end; f0 += GWB) {
        __syncthreads();
        for (int i = tid; i < GWB * GJT; i += 128) {
            int j = i & (GJT - 1), r = i / GJT;
            int col = j0 + j;
            float w = (col < ACTW) ? mbw[(size_t)(f0 + r) * ACTW + col] : 0.f;
            sw[r * GJT + j] = pack2(w, w);
        }
        __syncthreads();
        #pragma unroll 1
        for (int r = 0; r < GWB; r += 2) {
            size_t row1 = (size_t)(f0 + r + 1) * (NN / 2) + 2 * tid;
            a0B = __ldg(fbase + row1);
            a1B = __ldg(fbase + row1 + 1);
            #pragma unroll
            for (int j = 0; j < GJT; j++) {
                ull w = sw[r * GJT + j];
                ffma2(acc[j][0], a0A, w);
                ffma2(acc[j][1], a1A, w);
            }
            int fn = f0 + r + 2;
            if (fn < f_end) {
                size_t row2 = (size_t)fn * (NN / 2) + 2 * tid;
                a0A = __ldg(fbase + row2);
                a1A = __ldg(fbase + row2 + 1);
            }
            #pragma unroll
            for (int j = 0; j < GJT; j++) {
                ull w = sw[(r + 1) * GJT + j];
                ffma2(acc[j][0], a0B, w);
                ffma2(acc[j][1], a1B, w);
            }
        }
    }
    for (int j = 0; j < GJT; j++) {
        int col = j0 + j;
        if (col < ACTW) {
            float2* bp = reinterpret_cast<float2*>(g_act_part + ((size_t)kz * ACTW + col) * NN);
            bp[2 * tid]     = unpack(acc[j][0]);
            bp[2 * tid + 1] = unpack(acc[j][1]);
        }
    }
}

__global__ void kreduce_k() {
    int idx = blockIdx.x * 256 + threadIdx.x;
    if (idx < ACTW * NN) {
        float s = 0.f;
        #pragma unroll
        for (int z = 0; z < GKS; z++) s += g_act_part[(size_t)z * (ACTW * NN) + idx];
        g_act[idx] = s;
    }
}

// ---------------- minibatch discrimination (f32x2 over j-pairs) ----------------
__global__ void mbfeat_k() {
    __shared__ ull sb[DIMK][NN / 2];       // negated pairs {-act[2p], -act[2p+1]}
    int m = blockIdx.x, tid = threadIdx.x; // 512 threads
    float a[DIMK];
    #pragma unroll
    for (int d = 0; d < DIMK; d++)
        a[d] = g_act[(size_t)(m * DIMK + d) * NN + tid];
    for (int i = tid; i < DIMK * (NN / 2); i += NN) {
        int d = i / (NN / 2), p = i % (NN / 2);
        const float* src = g_act + (size_t)(m * DIMK + d) * NN + 2 * p;
        sb[d][p] = pack2(-src[0], -src[1]);
    }
    __syncthreads();
    ull ad[DIMK];
    #pragma unroll
    for (int d = 0; d < DIMK; d++) ad[d] = pack2(a[d], a[d]);
    float s = 0.f;
    for (int p = 0; p < NN / 2; p++) {
        ull l = abs2(add2(ad[0], sb[0][p]));
        #pragma unroll
        for (int d = 1; d < DIMK; d++)
            l = add2(l, abs2(add2(ad[d], sb[d][p])));
        float2 lf = unpack(l);
        s += __expf(-lf.x) + __expf(-lf.y);
    }
    g_feats[(size_t)m * NN + tid] = s;
}

// ---------------- final dot: partial over f-chunks, then reduce ----------------
__global__ void final_part_k(const float* __restrict__ fc_w) {
    int tid = threadIdx.x;                 // 256 (n-pairs)
    int base = blockIdx.x * FPERC;
    ull s2 = 0ULL;
    const ull* fb = reinterpret_cast<const ull*>(g_flat);
    #pragma unroll 4
    for (int r = 0; r < FPERC; r++) {
        int f = base + r;
        float w = __ldg(fc_w + f);
        ffma2(s2, __ldg(fb + (size_t)f * (NN / 2) + tid), pack2(w, w));
    }
    float2 v = unpack(s2);
    reinterpret_cast<float2*>(g_fpart + (size_t)blockIdx.x * NN)[tid] = v;
}

__global__ void final_red_k(const int* __restrict__ condition, const float* __restrict__ emb,
                            const float* __restrict__ cond_w, const float* __restrict__ cond_b,
                            const float* __restrict__ fc_w, const float* __restrict__ fc_b,
                            float* __restrict__ out) {
    int n = threadIdx.x;                   // 512
    float s = fc_b[0];
    for (int b = 0; b < FCH; b++) s += g_fpart[(size_t)b * NN + n];
    for (int m = 0; m < NUMK; m++) s += g_feats[(size_t)m * NN + n] * fc_w[FLAT + m];
    float e = emb[condition[n]];
    for (int i = 0; i < 50; i++) s += (e * cond_w[i] + cond_b[i]) * fc_w[FLAT + NUMK + i];
    out[n] = s;
}

// ---------------- launch ----------------
extern "C" void kernel_launch(void* const* d_in, const int* in_sizes, int n_in,
                              void* d_out, int out_size) {
    const float* ecg       = (const float*)d_in[0];
    const int*   condition = (const int*)  d_in[1];
    const float* w1        = (const float*)d_in[2];
    const float* b1        = (const float*)d_in[3];
    const float* u1        = (const float*)d_in[4];
    const float* w2        = (const float*)d_in[5];
    const float* b2        = (const float*)d_in[6];
    const float* u2        = (const float*)d_in[7];
    const float* w3        = (const float*)d_in[8];
    const float* b3        = (const float*)d_in[9];
    const float* u3        = (const float*)d_in[10];
    const float* emb       = (const float*)d_in[11];
    const float* cond_w    = (const float*)d_in[12];
    const float* cond_b    = (const float*)d_in[13];
    const float* mb_w      = (const float*)d_in[14];
    const float* fc_w      = (const float*)d_in[15];
    const float* fc_b      = (const float*)d_in[16];
    float* out = (float*)d_out;

    sigma_k<<<3, 256>>>(w1, u1, w2, u2, w3, u3);
    wprep_k<<<(1152 * C3 + 255) / 256, 256>>>(w1, w2, w3);
    ecgT_k<<<(LEADS * ER * NN + 255) / 256, 256>>>(ecg);
    conv1_k<<<dim3(T1 / 2, C1 / 16), 256>>>(b1);
    conv2_k<<<dim3((T2 + 1) / 2, C2 / 16), 256>>>(b2);
    conv3_k<<<dim3((T3 + 1) / 2, C3 / 16), 256>>>(b3);
    gemm_k<<<dim3((ACTW + GJT - 1) / GJT, GKS), 128>>>(mb_w);
    kreduce_k<<<(ACTW * NN + 255) / 256, 256>>>();
    mbfeat_k<<<NUMK, NN>>>();
    final_part_k<<<FCH, 256>>>(fc_w);
    final_red_k<<<1, NN>>>(condition, emb, cond_w, cond_b, fc_w, fc_b, out);
}

// round 8
// speedup vs baseline: 1.9953x; 1.0187x over previous
#include <cuda_runtime.h>
#include <math.h>

// ---------------- problem constants ----------------
#define NN      512
#define LIN     640
#define LEADS   3
#define T1      322
#define T2      161
#define T3      79
#define C1      64
#define C2      128
#define C3      256
#define ER      648     // ecgT padded rows (pad 4 each side)
#define X1R     336     // x1 padded rows (valid p=3..324)
#define X2R     168     // x2 padded rows (valid p=2..162)
#define FLAT    20224
#define NUMK    100
#define DIMK    5
#define ACTW    500
#define GJT     32
#define GKS     32
#define GKC     632     // 20224/32
#define GWB     158     // weight-stage rows; 632 = 4*158
#define FCH     64
#define FPERC   316     // 64*316 = 20224

// ---------------- device scratch (n-major layouts) ----------------
__device__ float g_inv_sigma[3];
__device__ float g_w1t[15 * C1];        // (ik, oc)
__device__ float g_w2t[448 * C2];
__device__ float g_w3t[1152 * C3];
__device__ float g_ecgT[LEADS * ER * NN];       // [lead][p][n]
__device__ float g_x1[C1 * X1R * NN];           // [ic][p][n]
__device__ float g_x2[C2 * X2R * NN];
__device__ float g_flat[FLAT * NN];             // [f][n], f = oc*79+t
__device__ float g_act_part[GKS * ACTW * NN];
__device__ float g_act[ACTW * NN];              // [j][n]
__device__ float g_feats[NUMK * NN];            // [m][n]
__device__ float g_fpart[FCH * NN];

typedef unsigned long long ull;

__device__ __forceinline__ void ffma2(ull& d, const ull a, const ull b) {
    asm("fma.rn.f32x2 %0, %1, %2, %0;" : "+l"(d) : "l"(a), "l"(b));
}
__device__ __forceinline__ ull add2(const ull a, const ull b) {
    ull d; asm("add.rn.f32x2 %0, %1, %2;" : "=l"(d) : "l"(a), "l"(b)); return d;
}
__device__ __forceinline__ ull abs2(const ull a) {
    return a & 0x7FFFFFFF7FFFFFFFULL;
}
__device__ __forceinline__ ull pack2(float x, float y) {
    ull u; asm("mov.b64 %0, {%1,%2};" : "=l"(u) : "f"(x), "f"(y)); return u;
}
__device__ __forceinline__ float2 unpack(ull u) {
    float2 f; asm("mov.b64 {%0,%1}, %2;" : "=f"(f.x), "=f"(f.y) : "l"(u)); return f;
}
__device__ __forceinline__ float leaky(float x) { return x >= 0.f ? x : 0.2f * x; }

// ---------------- spectral norm ----------------
__global__ void sigma_k(const float* __restrict__ w1, const float* __restrict__ u1,
                        const float* __restrict__ w2, const float* __restrict__ u2,
                        const float* __restrict__ w3, const float* __restrict__ u3) {
    const float* W; const float* U; int O, IK;
    if (blockIdx.x == 0)      { W = w1; U = u1; O = C1; IK = 15;   }
    else if (blockIdx.x == 1) { W = w2; U = u2; O = C2; IK = 448;  }
    else                      { W = w3; U = u3; O = C3; IK = 1152; }

    __shared__ float sv[1152];
    __shared__ float red[256];
    int tid = threadIdx.x;

    float local = 0.f;
    for (int j = tid; j < IK; j += 256) {
        float v = 0.f;
        for (int i = 0; i < O; i++) v += W[i * IK + j] * U[i];
        sv[j] = v;
        local += v * v;
    }
    red[tid] = local; __syncthreads();
    for (int s = 128; s > 0; s >>= 1) { if (tid < s) red[tid] += red[tid + s]; __syncthreads(); }
    float vscale = 1.f / (sqrtf(red[0]) + 1e-12f);
    __syncthreads();
    for (int j = tid; j < IK; j += 256) sv[j] *= vscale;
    __syncthreads();

    float local2 = 0.f;
    for (int i = tid; i < O; i += 256) {
        float t = 0.f;
        for (int j = 0; j < IK; j++) t += W[i * IK + j] * sv[j];
        local2 += t * t;
    }
    red[tid] = local2; __syncthreads();
    for (int s = 128; s > 0; s >>= 1) { if (tid < s) red[tid] += red[tid + s]; __syncthreads(); }
    if (tid == 0) {
        float nt = red[0];
        float sigma = nt / (sqrtf(nt) + 1e-12f);
        g_inv_sigma[blockIdx.x] = 1.f / sigma;
    }
}

// ---------------- weight transpose + scale ----------------
__global__ void wprep_k(const float* __restrict__ w1, const float* __restrict__ w2,
                        const float* __restrict__ w3) {
    int idx = blockIdx.x * 256 + threadIdx.x;
    if (idx < 1152 * C3) {
        int oc = idx % C3, r = idx / C3;
        g_w3t[idx] = w3[oc * 1152 + r] * g_inv_sigma[2];
    }
    if (idx < 448 * C2) {
        int oc = idx % C2, r = idx / C2;
        g_w2t[idx] = w2[oc * 448 + r] * g_inv_sigma[1];
    }
    if (idx < 15 * C1) {
        int oc = idx % C1, r = idx / C1;
        g_w1t[idx] = w1[oc * 15 + r] * g_inv_sigma[0];
    }
}

// ---------------- transpose ecg(N,L,3) -> ecgT[lead][p][n] ----------------
__global__ void ecgT_k(const float* __restrict__ ecg) {
    int idx = blockIdx.x * 256 + threadIdx.x;
    if (idx >= LEADS * ER * NN) return;
    int n = idx & (NN - 1);
    int rem = idx >> 9;
    int p = rem % ER;
    int lead = rem / ER;
    int t = p - 4;
    g_ecgT[idx] = (t >= 0 && t < LIN) ? ecg[(size_t)n * (LIN * LEADS) + t * LEADS + lead] : 0.f;
}

// ---------------- conv1: ecgT -> x1, k=5 s=2 p=4 ----------------
__global__ void conv1_k(const float* __restrict__ b1) {
    __shared__ ulonglong2 swv[15 * 8];     // [row][jh], pairs of duplicated weights
    int tid = threadIdx.x;                 // 256
    int t0 = blockIdx.x * 2;
    int oc0 = blockIdx.y * 16;
    for (int i = tid; i < 15 * 16; i += 256) {
        int j = i & 15, r = i >> 4;
        float w = g_w1t[r * C1 + oc0 + j];
        reinterpret_cast<ull*>(swv)[r * 16 + j] = pack2(w, w);
    }
    ull acc[16][2];
    #pragma unroll
    for (int j = 0; j < 16; j++) { float b = b1[oc0 + j]; acc[j][0] = acc[j][1] = pack2(b, b); }
    __syncthreads();
    #pragma unroll
    for (int lead = 0; lead < LEADS; lead++) {
        const ull* xp = reinterpret_cast<const ull*>(g_ecgT + ((size_t)lead * ER + 2 * t0) * NN) + tid;
        ull in[7];
        #pragma unroll
        for (int r = 0; r < 7; r++) in[r] = __ldg(xp + r * (NN / 2));
        #pragma unroll
        for (int k = 0; k < 5; k++) {
            #pragma unroll
            for (int jh = 0; jh < 8; jh++) {
                ulonglong2 w2 = swv[(lead * 5 + k) * 8 + jh];
                ffma2(acc[2 * jh][0],     in[k],     w2.x);
                ffma2(acc[2 * jh][1],     in[k + 2], w2.x);
                ffma2(acc[2 * jh + 1][0], in[k],     w2.y);
                ffma2(acc[2 * jh + 1][1], in[k + 2], w2.y);
            }
        }
    }
    #pragma unroll
    for (int j = 0; j < 16; j++) {
        int oc = oc0 + j;
        float2 v0 = unpack(acc[j][0]);
        float2 v1 = unpack(acc[j][1]);
        v0.x = leaky(v0.x); v0.y = leaky(v0.y);
        v1.x = leaky(v1.x); v1.y = leaky(v1.y);
        float2* o = reinterpret_cast<float2*>(g_x1 + ((size_t)oc * X1R + (t0 + 3)) * NN);
        o[tid] = v0;
        o[NN / 2 + tid] = v1;
    }
}

// ---------------- conv2: x1 -> x2, k=7 s=2 p=3, pipelined, LDS.128 weights ----------------
__global__ __launch_bounds__(256, 2) void conv2_k(const float* __restrict__ b2) {
    __shared__ ulonglong2 swv[32 * 7 * 8]; // 28.7 KB
    int tid = threadIdx.x;                 // 256
    int t0 = blockIdx.x * 2;
    int oc0 = blockIdx.y * 16;
    bool has_t1 = (t0 + 1) < T2;
    ull acc[16][2];
    #pragma unroll
    for (int j = 0; j < 16; j++) { float b = b2[oc0 + j]; acc[j][0] = acc[j][1] = pack2(b, b); }

    const ull* xb = reinterpret_cast<const ull*>(g_x1) + (size_t)2 * t0 * (NN / 2) + tid;
    ull bufA[9], bufB[9];
    #pragma unroll
    for (int r = 0; r < 9; r++) bufA[r] = __ldg(xb + r * (NN / 2));   // ic = 0

    for (int ch = 0; ch < 2; ch++) {
        int ic0 = ch * 32;
        __syncthreads();
        for (int i = tid; i < 32 * 7 * 16; i += 256) {
            int j = i & 15, row = i >> 4;
            float w = g_w2t[(ic0 * 7 + row) * C2 + oc0 + j];
            reinterpret_cast<ull*>(swv)[row * 16 + j] = pack2(w, w);
        }
        __syncthreads();
        #pragma unroll 1
        for (int icl = 0; icl < 32; icl += 2) {
            const ull* xpB = xb + (size_t)(ic0 + icl + 1) * X1R * (NN / 2);
            #pragma unroll
            for (int r = 0; r < 9; r++) bufB[r] = __ldg(xpB + r * (NN / 2));
            #pragma unroll
            for (int k = 0; k < 7; k++)
                #pragma unroll
                for (int jh = 0; jh < 8; jh++) {
                    ulonglong2 w2 = swv[(icl * 7 + k) * 8 + jh];
                    ffma2(acc[2 * jh][0],     bufA[k],     w2.x);
                    ffma2(acc[2 * jh][1],     bufA[k + 2], w2.x);
                    ffma2(acc[2 * jh + 1][0], bufA[k],     w2.y);
                    ffma2(acc[2 * jh + 1][1], bufA[k + 2], w2.y);
                }
            int nic = ic0 + icl + 2;
            if (nic < C1) {
                const ull* xpA = xb + (size_t)nic * X1R * (NN / 2);
                #pragma unroll
                for (int r = 0; r < 9; r++) bufA[r] = __ldg(xpA + r * (NN / 2));
            }
            #pragma unroll
            for (int k = 0; k < 7; k++)
                #pragma unroll
                for (int jh = 0; jh < 8; jh++) {
                    ulonglong2 w2 = swv[((icl + 1) * 7 + k) * 8 + jh];
                    ffma2(acc[2 * jh][0],     bufB[k],     w2.x);
                    ffma2(acc[2 * jh][1],     bufB[k + 2], w2.x);
                    ffma2(acc[2 * jh + 1][0], bufB[k],     w2.y);
                    ffma2(acc[2 * jh + 1][1], bufB[k + 2], w2.y);
                }
        }
    }
    #pragma unroll
    for (int j = 0; j < 16; j++) {
        int oc = oc0 + j;
        float2 v0 = unpack(acc[j][0]);
        float2 v1 = unpack(acc[j][1]);
        v0.x = leaky(v0.x); v0.y = leaky(v0.y);
        v1.x = leaky(v1.x); v1.y = leaky(v1.y);
        float2* o = reinterpret_cast<float2*>(g_x2 + ((size_t)oc * X2R + (t0 + 2)) * NN);
        o[tid] = v0;
        if (has_t1) o[NN / 2 + tid] = v1;
    }
}

// ---------------- conv3: x2 -> flat, k=9 s=2 p=2, pipelined, LDS.128 weights ----------------
__global__ __launch_bounds__(256, 2) void conv3_k(const float* __restrict__ b3) {
    __shared__ ulonglong2 swv[32 * 9 * 8]; // 36.9 KB
    int tid = threadIdx.x;                 // 256
    int t0 = blockIdx.x * 2;
    int oc0 = blockIdx.y * 16;
    bool has_t1 = (t0 + 1) < T3;
    ull acc[16][2];
    #pragma unroll
    for (int j = 0; j < 16; j++) { float b = b3[oc0 + j]; acc[j][0] = acc[j][1] = pack2(b, b); }

    const ull* xb = reinterpret_cast<const ull*>(g_x2) + (size_t)2 * t0 * (NN / 2) + tid;
    ull bufA[11], bufB[11];
    #pragma unroll
    for (int r = 0; r < 11; r++) bufA[r] = __ldg(xb + r * (NN / 2));  // ic = 0

    for (int ch = 0; ch < 4; ch++) {
        int ic0 = ch * 32;
        __syncthreads();
        for (int i = tid; i < 32 * 9 * 16; i += 256) {
            int j = i & 15, row = i >> 4;
            float w = g_w3t[(ic0 * 9 + row) * C3 + oc0 + j];
            reinterpret_cast<ull*>(swv)[row * 16 + j] = pack2(w, w);
        }
        __syncthreads();
        #pragma unroll 1
        for (int icl = 0; icl < 32; icl += 2) {
            const ull* xpB = xb + (size_t)(ic0 + icl + 1) * X2R * (NN / 2);
            #pragma unroll
            for (int r = 0; r < 11; r++) bufB[r] = __ldg(xpB + r * (NN / 2));
            #pragma unroll
            for (int k = 0; k < 9; k++)
                #pragma unroll
                for (int jh = 0; jh < 8; jh++) {
                    ulonglong2 w2 = swv[(icl * 9 + k) * 8 + jh];
                    ffma2(acc[2 * jh][0],     bufA[k],     w2.x);
                    ffma2(acc[2 * jh][1],     bufA[k + 2], w2.x);
                    ffma2(acc[2 * jh + 1][0], bufA[k],     w2.y);
                    ffma2(acc[2 * jh + 1][1], bufA[k + 2], w2.y);
                }
            int nic = ic0 + icl + 2;
            if (nic < C2) {
                const ull* xpA = xb + (size_t)nic * X2R * (NN / 2);
                #pragma unroll
                for (int r = 0; r < 11; r++) bufA[r] = __ldg(xpA + r * (NN / 2));
            }
            #pragma unroll
            for (int k = 0; k < 9; k++)
                #pragma unroll
                for (int jh = 0; jh < 8; jh++) {
                    ulonglong2 w2 = swv[((icl + 1) * 9 + k) * 8 + jh];
                    ffma2(acc[2 * jh][0],     bufB[k],     w2.x);
                    ffma2(acc[2 * jh][1],     bufB[k + 2], w2.x);
                    ffma2(acc[2 * jh + 1][0], bufB[k],     w2.y);
                    ffma2(acc[2 * jh + 1][1], bufB[k + 2], w2.y);
                }
        }
    }
    #pragma unroll
    for (int j = 0; j < 16; j++) {
        int oc = oc0 + j;
        float2 v0 = unpack(acc[j][0]);
        float2 v1 = unpack(acc[j][1]);
        v0.x = leaky(v0.x); v0.y = leaky(v0.y);
        v1.x = leaky(v1.x); v1.y = leaky(v1.y);
        float2* o = reinterpret_cast<float2*>(g_flat + ((size_t)oc * T3 + t0) * NN);
        o[tid] = v0;
        if (has_t1) o[NN / 2 + tid] = v1;
    }
}

// ---------------- GEMM: act[j][n] = sum_f mb_w[f][j] * flat[f][n], split-K, LDS.128 ----------------
__global__ __launch_bounds__(128, 3) void gemm_k(const float* __restrict__ mbw) {
    __shared__ ulonglong2 swv[GWB * 16];   // 40.4 KB
    int tid = threadIdx.x;                 // 128; each thread covers 4 n
    int j0 = blockIdx.x * GJT;
    int kz = blockIdx.y;
    int f_begin = kz * GKC, f_end = f_begin + GKC;
    ull acc[GJT][2];
    #pragma unroll
    for (int j = 0; j < GJT; j++) acc[j][0] = acc[j][1] = 0ULL;

    const ull* fbase = reinterpret_cast<const ull*>(g_flat);
    ull a0A = __ldg(fbase + (size_t)f_begin * (NN / 2) + 2 * tid);
    ull a1A = __ldg(fbase + (size_t)f_begin * (NN / 2) + 2 * tid + 1);
    ull a0B, a1B;

    for (int f0 = f_begin; f0 < f_end; f0 += GWB) {
        __syncthreads();
        for (int i = tid; i < GWB * GJT; i += 128) {
            int j = i & (GJT - 1), r = i / GJT;
            int col = j0 + j;
            float w = (col < ACTW) ? mbw[(size_t)(f0 + r) * ACTW + col] : 0.f;
            reinterpret_cast<ull*>(swv)[r * GJT + j] = pack2(w, w);
        }
        __syncthreads();
        #pragma unroll 1
        for (int r = 0; r < GWB; r += 2) {
            size_t row1 = (size_t)(f0 + r + 1) * (NN / 2) + 2 * tid;
            a0B = __ldg(fbase + row1);
            a1B = __ldg(fbase + row1 + 1);
            #pragma unroll
            for (int jh = 0; jh < 16; jh++) {
                ulonglong2 w2 = swv[r * 16 + jh];
                ffma2(acc[2 * jh][0],     a0A, w2.x);
                ffma2(acc[2 * jh][1],     a1A, w2.x);
                ffma2(acc[2 * jh + 1][0], a0A, w2.y);
                ffma2(acc[2 * jh + 1][1], a1A, w2.y);
            }
            int fn = f0 + r + 2;
            if (fn < f_end) {
                size_t row2 = (size_t)fn * (NN / 2) + 2 * tid;
                a0A = __ldg(fbase + row2);
                a1A = __ldg(fbase + row2 + 1);
            }
            #pragma unroll
            for (int jh = 0; jh < 16; jh++) {
                ulonglong2 w2 = swv[(r + 1) * 16 + jh];
                ffma2(acc[2 * jh][0],     a0B, w2.x);
                ffma2(acc[2 * jh][1],     a1B, w2.x);
                ffma2(acc[2 * jh + 1][0], a0B, w2.y);
                ffma2(acc[2 * jh + 1][1], a1B, w2.y);
            }
        }
    }
    for (int j = 0; j < GJT; j++) {
        int col = j0 + j;
        if (col < ACTW) {
            float2* bp = reinterpret_cast<float2*>(g_act_part + ((size_t)kz * ACTW + col) * NN);
            bp[2 * tid]     = unpack(acc[j][0]);
            bp[2 * tid + 1] = unpack(acc[j][1]);
        }
    }
}

__global__ void kreduce_k() {
    int idx = blockIdx.x * 256 + threadIdx.x;
    if (idx < ACTW * NN) {
        float s = 0.f;
        #pragma unroll
        for (int z = 0; z < GKS; z++) s += g_act_part[(size_t)z * (ACTW * NN) + idx];
        g_act[idx] = s;
    }
}

// ---------------- minibatch discrimination (f32x2 over j-pairs) ----------------
__global__ void mbfeat_k() {
    __shared__ ull sb[DIMK][NN / 2];       // negated pairs {-act[2p], -act[2p+1]}
    int m = blockIdx.x, tid = threadIdx.x; // 512 threads
    float a[DIMK];
    #pragma unroll
    for (int d = 0; d < DIMK; d++)
        a[d] = g_act[(size_t)(m * DIMK + d) * NN + tid];
    for (int i = tid; i < DIMK * (NN / 2); i += NN) {
        int d = i / (NN / 2), p = i % (NN / 2);
        const float* src = g_act + (size_t)(m * DIMK + d) * NN + 2 * p;
        sb[d][p] = pack2(-src[0], -src[1]);
    }
    __syncthreads();
    ull ad[DIMK];
    #pragma unroll
    for (int d = 0; d < DIMK; d++) ad[d] = pack2(a[d], a[d]);
    float s = 0.f;
    for (int p = 0; p < NN / 2; p++) {
        ull l = abs2(add2(ad[0], sb[0][p]));
        #pragma unroll
        for (int d = 1; d < DIMK; d++)
            l = add2(l, abs2(add2(ad[d], sb[d][p])));
        float2 lf = unpack(l);
        s += __expf(-lf.x) + __expf(-lf.y);
    }
    g_feats[(size_t)m * NN + tid] = s;
}

// ---------------- final dot: partial over f-chunks, then reduce ----------------
__global__ void final_part_k(const float* __restrict__ fc_w) {
    int tid = threadIdx.x;                 // 256 (n-pairs)
    int base = blockIdx.x * FPERC;
    ull s2 = 0ULL;
    const ull* fb = reinterpret_cast<const ull*>(g_flat);
    #pragma unroll 4
    for (int r = 0; r < FPERC; r++) {
        int f = base + r;
        float w = __ldg(fc_w + f);
        ffma2(s2, __ldg(fb + (size_t)f * (NN / 2) + tid), pack2(w, w));
    }
    float2 v = unpack(s2);
    reinterpret_cast<float2*>(g_fpart + (size_t)blockIdx.x * NN)[tid] = v;
}

__global__ void final_red_k(const int* __restrict__ condition, const float* __restrict__ emb,
                            const float* __restrict__ cond_w, const float* __restrict__ cond_b,
                            const float* __restrict__ fc_w, const float* __restrict__ fc_b,
                            float* __restrict__ out) {
    int n = threadIdx.x;                   // 512
    float s = fc_b[0];
    for (int b = 0; b < FCH; b++) s += g_fpart[(size_t)b * NN + n];
    for (int m = 0; m < NUMK; m++) s += g_feats[(size_t)m * NN + n] * fc_w[FLAT + m];
    float e = emb[condition[n]];
    for (int i = 0; i < 50; i++) s += (e * cond_w[i] + cond_b[i]) * fc_w[FLAT + NUMK + i];
    out[n] = s;
}

// ---------------- launch ----------------
extern "C" void kernel_launch(void* const* d_in, const int* in_sizes, int n_in,
                              void* d_out, int out_size) {
    const float* ecg       = (const float*)d_in[0];
    const int*   condition = (const int*)  d_in[1];
    const float* w1        = (const float*)d_in[2];
    const float* b1        = (const float*)d_in[3];
    const float* u1        = (const float*)d_in[4];
    const float* w2        = (const float*)d_in[5];
    const float* b2        = (const float*)d_in[6];
    const float* u2        = (const float*)d_in[7];
    const float* w3        = (const float*)d_in[8];
    const float* b3        = (const float*)d_in[9];
    const float* u3        = (const float*)d_in[10];
    const float* emb       = (const float*)d_in[11];
    const float* cond_w    = (const float*)d_in[12];
    const float* cond_b    = (const float*)d_in[13];
    const float* mb_w      = (const float*)d_in[14];
    const float* fc_w      = (const float*)d_in[15];
    const float* fc_b      = (const float*)d_in[16];
    float* out = (float*)d_out;

    sigma_k<<<3, 256>>>(w1, u1, w2, u2, w3, u3);
    wprep_k<<<(1152 * C3 + 255) / 256, 256>>>(w1, w2, w3);
    ecgT_k<<<(LEADS * ER * NN + 255) / 256, 256>>>(ecg);
    conv1_k<<<dim3(T1 / 2, C1 / 16), 256>>>(b1);
    conv2_k<<<dim3((T2 + 1) / 2, C2 / 16), 256>>>(b2);
    conv3_k<<<dim3((T3 + 1) / 2, C3 / 16), 256>>>(b3);
    gemm_k<<<dim3((ACTW + GJT - 1) / GJT, GKS), 128>>>(mb_w);
    kreduce_k<<<(ACTW * NN + 255) / 256, 256>>>();
    mbfeat_k<<<NUMK, NN>>>();
    final_part_k<<<FCH, 256>>>(fc_w);
    final_red_k<<<1, NN>>>(condition, emb, cond_w, cond_b, fc_w, fc_b, out);
}